// round 17
// baseline (speedup 1.0000x reference)
#include <cuda_runtime.h>
#include <math.h>

#define BB 64
#define NN 256
#define DD 128
#define HH 8
#define FF 512
#define EPSV 1e-5

typedef unsigned long long u64;

// ------- packed f32x2 helpers (sm_103a FFMA2 path, PTX-only) -------
__device__ __forceinline__ u64 pack2(float lo, float hi) {
    u64 r; asm("mov.b64 %0, {%1, %2};" : "=l"(r) : "f"(lo), "f"(hi)); return r;
}
__device__ __forceinline__ u64 fma2(u64 a, u64 b, u64 c) {
    u64 d; asm("fma.rn.f32x2 %0, %1, %2, %3;" : "=l"(d) : "l"(a), "l"(b), "l"(c)); return d;
}
__device__ __forceinline__ u64 mul2(u64 a, u64 b) {
    u64 d; asm("mul.rn.f32x2 %0, %1, %2;" : "=l"(d) : "l"(a), "l"(b)); return d;
}
__device__ __forceinline__ float2 unpack2(u64 v) {
    float2 r; asm("mov.b64 {%0, %1}, %2;" : "=f"(r.x), "=f"(r.y) : "l"(v)); return r;
}

// ------- scratch (device globals; no allocations anywhere) -------
__device__ float g_Q[BB * NN * DD];
__device__ float g_K[BB * NN * DD];
__device__ float g_V[BB * NN * DD];
__device__ float g_heads[BB * NN * DD];
__device__ float g_x0[BB * NN * DD];
__device__ float g_hdn[BB * NN * FF];
__device__ float g_y0[BB * NN * DD];
__device__ float g_ps[2][BB * 8];
__device__ float g_pq[2][BB * 8];

// select arr[idx] for idx in 0..7 without dynamic indexing
#define SEL8(arr, idx, out) do {                                   \
    float _s0 = ((idx) & 1) ? (arr)[1] : (arr)[0];                 \
    float _s1 = ((idx) & 1) ? (arr)[3] : (arr)[2];                 \
    float _s2 = ((idx) & 1) ? (arr)[5] : (arr)[4];                 \
    float _s3 = ((idx) & 1) ? (arr)[7] : (arr)[6];                 \
    float _t0 = ((idx) & 2) ? _s1 : _s0;                           \
    float _t1 = ((idx) & 2) ? _s3 : _s2;                           \
    (out) = ((idx) & 4) ? _t1 : _t0;                               \
} while (0)

__device__ __forceinline__ void ln_finalize(int which, int b, float* mu, float* iv) {
    double s = 0.0, q = 0.0;
#pragma unroll
    for (int i = 0; i < 8; i++) {
        s += (double)g_ps[which][b * 8 + i];
        q += (double)g_pq[which][b * 8 + i];
    }
    double n = (double)(NN * DD);
    double mean = s / n;
    double var = (q - s * s / n) / (n - 1.0);
    *mu = (float)mean;
    *iv = (float)(1.0 / sqrt(var + EPSV));
}

// 4-row x 4-col x 4-k micro-tile, packed FFMA2 (acc2 = u64[4][2])
#define MICRO44P(acc2, xrow, xstride, kofs, ws, lane)                       \
    do {                                                                    \
        float4 xv[4];                                                       \
        _Pragma("unroll")                                                   \
        for (int _r = 0; _r < 4; _r++)                                      \
            xv[_r] = *(const float4*)&(xrow)[_r * (xstride) + (kofs)];      \
        _Pragma("unroll")                                                   \
        for (int _j = 0; _j < 4; _j++) {                                    \
            ulonglong2 wq = *(const ulonglong2*)&(ws)[(dl + _j) * 128 + (lane) * 4]; \
            _Pragma("unroll")                                               \
            for (int _r = 0; _r < 4; _r++) {                                \
                float xj = (_j == 0) ? xv[_r].x : (_j == 1) ? xv[_r].y      \
                         : (_j == 2) ? xv[_r].z : xv[_r].w;                 \
                u64 x2 = pack2(xj, xj);                                     \
                acc2[_r][0] = fma2(x2, wq.x, acc2[_r][0]);                  \
                acc2[_r][1] = fma2(x2, wq.y, acc2[_r][1]);                  \
            }                                                               \
        }                                                                   \
    } while (0)

// ============ K1: Q/K/V projections (32 rows/block, 4x4 tile, prefetch) ====
__global__ __launch_bounds__(256) void k1_qkv(const float* __restrict__ hem,
                                              const float* __restrict__ Wq,
                                              const float* __restrict__ Wk,
                                              const float* __restrict__ Wv) {
    __shared__ __align__(16) float ws[32 * 128];
    __shared__ __align__(16) float xs[32 * 128];
    int b = blockIdx.y, n0 = blockIdx.x * 32, t = threadIdx.x;
    int w = t >> 5, lane = t & 31;

    float4 pf[4];
#pragma unroll
    for (int i = 0; i < 4; i++) {
        int e = t + i * 256, h = e >> 7, dl = (e >> 2) & 31, k4 = e & 3;
        pf[i] = ((const float4*)Wq)[h * 512 + dl * 4 + k4];
    }
    const float4* hem4 = (const float4*)(hem + ((size_t)b * NN + n0) * DD);
    for (int e = t; e < 1024; e += 256)
        ((float4*)xs)[e] = hem4[e];
    const float* xrow = &xs[(w * 4) * 128];

    u64 acc2[4][2] = {};
    for (int s = 0; s < 12; s++) {
        int wi = s >> 2, dc = s & 3;
        __syncthreads();
#pragma unroll
        for (int i = 0; i < 4; i++) {
            int e = t + i * 256, h = e >> 7, dl = (e >> 2) & 31, k4 = e & 3;
            ((float4*)ws)[dl * 32 + h * 4 + k4] = pf[i];
        }
        __syncthreads();
        if (s < 11) {
            int s2 = s + 1, wi2 = s2 >> 2, dc2 = s2 & 3;
            const float4* W4 = (wi2 == 0) ? (const float4*)Wq
                             : (wi2 == 1) ? (const float4*)Wk : (const float4*)Wv;
#pragma unroll
            for (int i = 0; i < 4; i++) {
                int e = t + i * 256, h = e >> 7, dl = (e >> 2) & 31, k4 = e & 3;
                pf[i] = W4[h * 512 + (dc2 * 32 + dl) * 4 + k4];
            }
        }
#pragma unroll 2
        for (int dl = 0; dl < 32; dl += 4)
            MICRO44P(acc2, xrow, 128, dc * 32 + dl, ws, lane);
        if (dc == 3) {
            float* O = (wi == 0) ? g_Q : (wi == 1) ? g_K : g_V;
#pragma unroll
            for (int r = 0; r < 4; r++) {
                float2 lo = unpack2(acc2[r][0]), hi = unpack2(acc2[r][1]);
                *(float4*)&O[((size_t)b * NN + n0 + w * 4 + r) * DD + lane * 4] =
                    make_float4(lo.x, lo.y, hi.x, hi.y);
                acc2[r][0] = 0ull; acc2[r][1] = 0ull;
            }
        }
    }
}

// ==== K2 (flash): scores + score_aggr MLP + online softmax + P@V -> heads ====
__global__ __launch_bounds__(256) void k2_flash(const float* __restrict__ route,
                                                const float* __restrict__ sw1,
                                                const float* __restrict__ sb1,
                                                const float* __restrict__ sw2,
                                                const float* __restrict__ sb2,
                                                float* __restrict__ rout) {
    __shared__ __align__(16) float Qs[8 * 128];
    __shared__ __align__(16) float Ks[32 * 132];
    __shared__ __align__(16) float Vs[32 * 128];
    __shared__ float ps[8 * 8 * 33];
    __shared__ __align__(16) float w1s[256];
    __shared__ __align__(16) float w2s[128];
    __shared__ float b1s[16], b2s[8];

    int b = blockIdx.y, n0 = blockIdx.x * 8, t = threadIdx.x;
    int w = t >> 5, lane = t & 31;
    int n = n0 + w;
    int hme = lane >> 2;

    {
        int m = t >> 5, d4 = (t & 31) * 4;
        *(float4*)&Qs[m * 128 + d4] =
            *(const float4*)&g_Q[((size_t)b * NN + n0 + m) * DD + d4];
    }
    w1s[t] = sw1[t];
    if (t < 128) w2s[t] = sw2[t];
    if (t < 16) b1s[t] = sb1[t];
    if (t < 8) b2s[t] = sb2[t];

    float M[8], L[8];   // L = per-lane partial expsum (summed across lanes at end)
#pragma unroll
    for (int h = 0; h < 8; h++) { M[h] = -1e30f; L[h] = 0.f; }
    u64 pv01 = 0ull, pv23 = 0ull;

#pragma unroll 1
    for (int mc = 0; mc < 8; mc++) {
        __syncthreads();
#pragma unroll
        for (int i = 0; i < 4; i++) {
            int e = t + i * 256;
            int m = e >> 5, d4 = (e & 31) * 4;
            size_t gb = ((size_t)b * NN + mc * 32 + m) * DD + d4;
            *(float4*)&Ks[m * 132 + d4] = *(const float4*)&g_K[gb];
            *(float4*)&Vs[m * 128 + d4] = *(const float4*)&g_V[gb];
        }
        __syncthreads();

        // ---- scores s[h]: packed dot products (Q,K pair naturally) ----
        float s[8];
#pragma unroll
        for (int h = 0; h < 8; h++) {
            const ulonglong2* kp = (const ulonglong2*)&Ks[lane * 132 + h * 16];
            const ulonglong2* qp = (const ulonglong2*)&Qs[w * 128 + h * 16];
            ulonglong2 k01 = kp[0], k23 = kp[1], k45 = kp[2], k67 = kp[3];
            ulonglong2 q01 = qp[0], q23 = qp[1], q45 = qp[2], q67 = qp[3];
            u64 sa = fma2(q01.x, k01.x, 0ull);
            u64 sb = fma2(q01.y, k01.y, 0ull);
            sa = fma2(q23.x, k23.x, sa);
            sb = fma2(q23.y, k23.y, sb);
            sa = fma2(q45.x, k45.x, sa);
            sb = fma2(q45.y, k45.y, sb);
            sa = fma2(q67.x, k67.x, sa);
            sb = fma2(q67.y, k67.y, sb);
            float2 fa = unpack2(sa), fb = unpack2(sb);
            s[h] = (fa.x + fa.y) + (fb.x + fb.y);
        }
        // ---- route passthrough ----
        float r[8];
#pragma unroll
        for (int h = 0; h < 8; h++) {
            size_t ri = (((size_t)h * BB + b) * NN + n) * NN + mc * 32 + lane;
            r[h] = route[ri];
            if (rout) rout[ri] = r[h];
        }

        // ---- score_aggr MLP: 16 -> relu16 -> 8, packed ----
        u64 hd2[8];
#pragma unroll
        for (int jp = 0; jp < 8; jp++) hd2[jp] = pack2(b1s[2 * jp], b1s[2 * jp + 1]);
#pragma unroll
        for (int i = 0; i < 16; i++) {
            float xi = (i < 8) ? s[i] : r[i - 8];
            u64 x2 = pack2(xi, xi);
            const ulonglong2* wp = (const ulonglong2*)&w1s[i * 16];
            ulonglong2 wa = wp[0], wb = wp[1], wc = wp[2], wd = wp[3];
            hd2[0] = fma2(x2, wa.x, hd2[0]); hd2[1] = fma2(x2, wa.y, hd2[1]);
            hd2[2] = fma2(x2, wb.x, hd2[2]); hd2[3] = fma2(x2, wb.y, hd2[3]);
            hd2[4] = fma2(x2, wc.x, hd2[4]); hd2[5] = fma2(x2, wc.y, hd2[5]);
            hd2[6] = fma2(x2, wd.x, hd2[6]); hd2[7] = fma2(x2, wd.y, hd2[7]);
        }
        float hdv[16];
#pragma unroll
        for (int jp = 0; jp < 8; jp++) {
            float2 f = unpack2(hd2[jp]);
            hdv[2 * jp] = fmaxf(f.x, 0.f);
            hdv[2 * jp + 1] = fmaxf(f.y, 0.f);
        }
        u64 a2[4];
#pragma unroll
        for (int hp = 0; hp < 4; hp++) a2[hp] = pack2(b2s[2 * hp], b2s[2 * hp + 1]);
#pragma unroll
        for (int j = 0; j < 16; j++) {
            u64 h2 = pack2(hdv[j], hdv[j]);
            const ulonglong2* wp = (const ulonglong2*)&w2s[j * 8];
            ulonglong2 wa = wp[0], wb = wp[1];
            a2[0] = fma2(h2, wa.x, a2[0]); a2[1] = fma2(h2, wa.y, a2[1]);
            a2[2] = fma2(h2, wb.x, a2[2]); a2[3] = fma2(h2, wb.y, a2[3]);
        }
        float a[8];
#pragma unroll
        for (int hp = 0; hp < 4; hp++) {
            float2 f = unpack2(a2[hp]);
            a[2 * hp] = f.x; a[2 * hp + 1] = f.y;
        }

        // ---- online softmax: max butterfly only (sum deferred) ----
        float cm[8];
#pragma unroll
        for (int h = 0; h < 8; h++) cm[h] = a[h];
#pragma unroll
        for (int o = 16; o > 0; o >>= 1)
#pragma unroll
            for (int h = 0; h < 8; h++)
                cm[h] = fmaxf(cm[h], __shfl_xor_sync(0xffffffffu, cm[h], o));
        float sc[8];
#pragma unroll
        for (int h = 0; h < 8; h++) {
            float nm = fmaxf(M[h], cm[h]);
            float ev = __expf(a[h] - nm);
            ps[(w * 8 + h) * 33 + lane] = ev;
            sc[h] = __expf(M[h] - nm);      // warp-uniform
            L[h] = L[h] * sc[h] + ev;       // per-lane partial
            M[h] = nm;
        }
        float sown;
        SEL8(sc, hme, sown);
        {
            u64 s2 = pack2(sown, sown);
            pv01 = mul2(pv01, s2);
            pv23 = mul2(pv23, s2);
        }
        __syncwarp();

        // ---- P @ V accumulate, packed ----
#pragma unroll
        for (int m = 0; m < 32; m++) {
            float p = ps[(w * 8 + hme) * 33 + m];
            u64 p2 = pack2(p, p);
            ulonglong2 vq = *(const ulonglong2*)&Vs[m * 128 + lane * 4];
            pv01 = fma2(p2, vq.x, pv01);
            pv23 = fma2(p2, vq.y, pv23);
        }
        __syncwarp();
    }
    // final cross-lane sum of L partials
#pragma unroll
    for (int o = 16; o > 0; o >>= 1)
#pragma unroll
        for (int h = 0; h < 8; h++)
            L[h] += __shfl_xor_sync(0xffffffffu, L[h], o);
    float Lown;
    SEL8(L, hme, Lown);
    float inv = 1.f / Lown;
    float2 v01 = unpack2(pv01), v23 = unpack2(pv23);
    *(float4*)&g_heads[((size_t)b * NN + n) * DD + lane * 4] =
        make_float4(v01.x * inv, v01.y * inv, v23.x * inv, v23.y * inv);
}

// ============ K4: heads @ W_out + h_em -> x0, LN partials[0], prefetch ======
__global__ __launch_bounds__(256) void k4_out(const float* __restrict__ Wo,
                                              const float* __restrict__ hem) {
    __shared__ __align__(16) float ws[32 * 128];
    __shared__ __align__(16) float xs[32 * 128];
    __shared__ float red[16];
    int b = blockIdx.y, n0 = blockIdx.x * 32, t = threadIdx.x;
    int w = t >> 5, lane = t & 31;
    const float4* Wo4 = (const float4*)Wo;
    float4 pf[4];
#pragma unroll
    for (int i = 0; i < 4; i++)
        pf[i] = Wo4[(w + i * 8) * 32 + lane];
    const float4* hd4 = (const float4*)(g_heads + ((size_t)b * NN + n0) * DD);
    for (int e = t; e < 1024; e += 256)
        ((float4*)xs)[e] = hd4[e];
    const float* xrow = &xs[(w * 4) * 128];
    u64 acc2[4][2] = {};
    for (int kc = 0; kc < 4; kc++) {
        __syncthreads();
#pragma unroll
        for (int i = 0; i < 4; i++)
            ((float4*)ws)[(w + i * 8) * 32 + lane] = pf[i];
        __syncthreads();
        if (kc < 3) {
#pragma unroll
            for (int i = 0; i < 4; i++)
                pf[i] = Wo4[((kc + 1) * 32 + w + i * 8) * 32 + lane];
        }
#pragma unroll 2
        for (int dl = 0; dl < 32; dl += 4)
            MICRO44P(acc2, xrow, 128, kc * 32 + dl, ws, lane);
    }
    float ls = 0.f, lq = 0.f;
#pragma unroll
    for (int r = 0; r < 4; r++) {
        size_t base = ((size_t)b * NN + n0 + w * 4 + r) * DD + lane * 4;
        float4 he = *(const float4*)&hem[base];
        float2 lo = unpack2(acc2[r][0]), hi = unpack2(acc2[r][1]);
        float v0 = lo.x + he.x, v1 = lo.y + he.y;
        float v2 = hi.x + he.z, v3 = hi.y + he.w;
        *(float4*)&g_x0[base] = make_float4(v0, v1, v2, v3);
        ls += v0 + v1 + v2 + v3;
        lq += v0 * v0 + v1 * v1 + v2 * v2 + v3 * v3;
    }
#pragma unroll
    for (int o = 16; o > 0; o >>= 1) {
        ls += __shfl_xor_sync(0xffffffffu, ls, o);
        lq += __shfl_xor_sync(0xffffffffu, lq, o);
    }
    if (lane == 0) { red[w] = ls; red[8 + w] = lq; }
    __syncthreads();
    if (t == 0) {
        float s = 0.f, q = 0.f;
        for (int i = 0; i < 8; i++) { s += red[i]; q += red[8 + i]; }
        g_ps[0][b * 8 + blockIdx.x] = s;
        g_pq[0][b * 8 + blockIdx.x] = q;
    }
}

// ============ K6: x = LN(x0); hdn = relu(x @ ff_w1), prefetch ============
__global__ __launch_bounds__(256) void k6_ff1(const float* __restrict__ w1) {
    __shared__ __align__(16) float ws[32 * 128];
    __shared__ __align__(16) float xs[32 * 128];
    __shared__ float s_mu, s_iv;
    int b = blockIdx.y, n0 = blockIdx.x * 32, t = threadIdx.x;
    int w = t >> 5, lane = t & 31;
    const float4* w14 = (const float4*)w1;
    float4 pf[4];
#pragma unroll
    for (int i = 0; i < 4; i++)
        pf[i] = w14[(w + i * 8) * 128 + lane];      // ft=0, dc=0
    if (t == 0) ln_finalize(0, b, (float*)&s_mu, (float*)&s_iv);
    __syncthreads();
    float mu = s_mu, iv = s_iv;
    const float4* x04 = (const float4*)(g_x0 + ((size_t)b * NN + n0) * DD);
    for (int e = t; e < 1024; e += 256) {
        float4 v = x04[e];
        v.x = (v.x - mu) * iv; v.y = (v.y - mu) * iv;
        v.z = (v.z - mu) * iv; v.w = (v.w - mu) * iv;
        ((float4*)xs)[e] = v;
    }
    const float* xrow = &xs[(w * 4) * 128];
    u64 acc2[4][2] = {};
    for (int s = 0; s < 16; s++) {
        int ft = s >> 2, dc = s & 3;
        __syncthreads();
#pragma unroll
        for (int i = 0; i < 4; i++)
            ((float4*)ws)[(w + i * 8) * 32 + lane] = pf[i];
        __syncthreads();
        if (s < 15) {
            int s2 = s + 1, ft2 = s2 >> 2, dc2 = s2 & 3;
#pragma unroll
            for (int i = 0; i < 4; i++)
                pf[i] = w14[(dc2 * 32 + w + i * 8) * 128 + ft2 * 32 + lane];
        }
#pragma unroll 2
        for (int dl = 0; dl < 32; dl += 4)
            MICRO44P(acc2, xrow, 128, dc * 32 + dl, ws, lane);
        if (dc == 3) {
#pragma unroll
            for (int r = 0; r < 4; r++) {
                float2 lo = unpack2(acc2[r][0]), hi = unpack2(acc2[r][1]);
                *(float4*)&g_hdn[((size_t)b * NN + n0 + w * 4 + r) * FF + ft * 128 + lane * 4] =
                    make_float4(fmaxf(lo.x, 0.f), fmaxf(lo.y, 0.f),
                                fmaxf(hi.x, 0.f), fmaxf(hi.y, 0.f));
                acc2[r][0] = 0ull; acc2[r][1] = 0ull;
            }
        }
    }
}

// ============ K7: y0 = hdn @ ff_w2 + x, LN partials[1], prefetch ============
__global__ __launch_bounds__(256) void k7_ff2(const float* __restrict__ w2) {
    __shared__ __align__(16) float ws[32 * 128];
    __shared__ __align__(16) float hs[32 * 32];
    __shared__ float red[16];
    __shared__ float s_mu, s_iv;
    int b = blockIdx.y, n0 = blockIdx.x * 32, t = threadIdx.x;
    int w = t >> 5, lane = t & 31;
    const float4* w24 = (const float4*)w2;
    const float4* hdn4 = (const float4*)g_hdn;
    int hrow = t >> 3, hc = t & 7;
    float4 pfw[4], pfh;
#pragma unroll
    for (int i = 0; i < 4; i++)
        pfw[i] = w24[(w + i * 8) * 32 + lane];
    pfh = hdn4[((size_t)b * NN + n0 + hrow) * (FF / 4) + hc];
    if (t == 0) ln_finalize(0, b, (float*)&s_mu, (float*)&s_iv);
    u64 acc2[4][2] = {};
    for (int kc = 0; kc < 16; kc++) {
        __syncthreads();
#pragma unroll
        for (int i = 0; i < 4; i++)
            ((float4*)ws)[(w + i * 8) * 32 + lane] = pfw[i];
        ((float4*)hs)[t] = pfh;
        __syncthreads();
        if (kc < 15) {
#pragma unroll
            for (int i = 0; i < 4; i++)
                pfw[i] = w24[((kc + 1) * 32 + w + i * 8) * 32 + lane];
            pfh = hdn4[((size_t)b * NN + n0 + hrow) * (FF / 4) + (kc + 1) * 8 + hc];
        }
#pragma unroll 2
        for (int dl = 0; dl < 32; dl += 4)
            MICRO44P(acc2, &hs[(w * 4) * 32], 32, dl, ws, lane);
    }
    float mu = s_mu, iv = s_iv;
    float ls = 0.f, lq = 0.f;
#pragma unroll
    for (int r = 0; r < 4; r++) {
        size_t base = ((size_t)b * NN + n0 + w * 4 + r) * DD + lane * 4;
        float4 xv = *(const float4*)&g_x0[base];
        float2 lo = unpack2(acc2[r][0]), hi = unpack2(acc2[r][1]);
        float v0 = lo.x + (xv.x - mu) * iv;
        float v1 = lo.y + (xv.y - mu) * iv;
        float v2 = hi.x + (xv.z - mu) * iv;
        float v3 = hi.y + (xv.w - mu) * iv;
        *(float4*)&g_y0[base] = make_float4(v0, v1, v2, v3);
        ls += v0 + v1 + v2 + v3;
        lq += v0 * v0 + v1 * v1 + v2 * v2 + v3 * v3;
    }
#pragma unroll
    for (int o = 16; o > 0; o >>= 1) {
        ls += __shfl_xor_sync(0xffffffffu, ls, o);
        lq += __shfl_xor_sync(0xffffffffu, lq, o);
    }
    if (lane == 0) { red[w] = ls; red[8 + w] = lq; }
    __syncthreads();
    if (t == 0) {
        float s = 0.f, q = 0.f;
        for (int i = 0; i < 8; i++) { s += red[i]; q += red[8 + i]; }
        g_ps[1][b * 8 + blockIdx.x] = s;
        g_pq[1][b * 8 + blockIdx.x] = q;
    }
}

// ============ K8: out1 = LN(y0) ============
__global__ __launch_bounds__(256) void k8_norm(float* __restrict__ out) {
    __shared__ float s_mu, s_iv;
    int i = blockIdx.x * 256 + threadIdx.x;
    int b = i >> 13;
    if (threadIdx.x == 0) ln_finalize(1, b, (float*)&s_mu, (float*)&s_iv);
    __syncthreads();
    float mu = s_mu, iv = s_iv;
    float4 v = ((const float4*)g_y0)[i];
    v.x = (v.x - mu) * iv; v.y = (v.y - mu) * iv;
    v.z = (v.z - mu) * iv; v.w = (v.w - mu) * iv;
    ((float4*)out)[i] = v;
}

// ============ launcher ============
extern "C" void kernel_launch(void* const* d_in, const int* in_sizes, int n_in,
                              void* d_out, int out_size) {
    const float* hem = (const float*)d_in[0];
    const float* route = (const float*)d_in[1];
    const float* Wq = (const float*)d_in[2];
    const float* Wk = (const float*)d_in[3];
    const float* Wv = (const float*)d_in[4];
    const float* Wo = (const float*)d_in[5];
    const float* sw1 = (const float*)d_in[6];
    const float* sb1 = (const float*)d_in[7];
    const float* sw2 = (const float*)d_in[8];
    const float* sb2 = (const float*)d_in[9];
    const float* fw1 = (const float*)d_in[10];
    const float* fw2 = (const float*)d_in[11];
    float* out = (float*)d_out;

    const long long OUT1 = (long long)BB * NN * DD;        // 2097152
    const long long ROUTE = (long long)HH * BB * NN * NN;  // 33554432
    float* rout = ((long long)out_size >= OUT1 + ROUTE) ? (out + OUT1) : (float*)0;

    dim3 g8(8, BB);
    dim3 g32(32, BB);

    k1_qkv<<<g8, 256>>>(hem, Wq, Wk, Wv);
    k2_flash<<<g32, 256>>>(route, sw1, sb1, sw2, sb2, rout);
    k4_out<<<g8, 256>>>(Wo, hem);
    k6_ff1<<<g8, 256>>>(fw1);
    k7_ff2<<<g8, 256>>>(fw2);
    k8_norm<<<2048, 256>>>(out);
}